// round 7
// baseline (speedup 1.0000x reference)
#include <cuda_runtime.h>
#include <math.h>

#define D        128
#define NRBF     20
#define MAX_ATOMS 40960
#define CHUNK    128   // pairs staged per block iteration (16 per warp)

// Scratch (alloc-free: __device__ globals)
__device__ __align__(16) float g_h[MAX_ATOMS * D];      // 20.5 MB
__device__ __align__(16) float g_agg[MAX_ATOMS * D];    // 20.5 MB
__device__ __align__(16) float g_WT[2][D * D];          // transposed W_in / W_out

typedef unsigned long long ull;

__device__ __forceinline__ ull pack2(float a, float b) {
    ull r; asm("mov.b64 %0, {%1,%2};" : "=l"(r) : "f"(a), "f"(b)); return r;
}
__device__ __forceinline__ float2 unpack2(ull v) {
    float2 f; asm("mov.b64 {%0,%1}, %2;" : "=f"(f.x), "=f"(f.y) : "l"(v)); return f;
}
__device__ __forceinline__ ull ffma2(ull a, ull b, ull c) {
    ull d; asm("fma.rn.f32x2 %0, %1, %2, %3;" : "=l"(d) : "l"(a), "l"(b), "l"(c)); return d;
}

__device__ __forceinline__ float ssp(float x) {
    // softplus(x) - ln2, fast+stable: max(x,0) + log(1+exp(-|x|)) - ln2
    float e = __expf(-fabsf(x));
    return fmaxf(x, 0.0f) + __logf(1.0f + e) - 0.69314718056f;
}

// Transpose W_in / W_out ([c][k] -> [k][c]) for coalesced conflict-free GEMM tiles.
__global__ void prep_kernel(const float* __restrict__ Win, const float* __restrict__ Wout) {
    int t = blockIdx.x * blockDim.x + threadIdx.x;
    if (t < D * D) {
        int c = t >> 7, k = t & 127;
        g_WT[0][k * D + c] = Win[t];
        g_WT[1][k * D + c] = Wout[t];
    }
}

__global__ void zero_kernel(int n4) {
    int t = blockIdx.x * blockDim.x + threadIdx.x;
    if (t < n4) reinterpret_cast<float4*>(g_agg)[t] = make_float4(0.f, 0.f, 0.f, 0.f);
}

// ===== GEMM: exact R5 version (known good) =====
// Y[r][c] = act( sum_k X[r][k]*W[c][k] + b[c] ), W pre-transposed [k][c] in g_WT[MODE].
// MODE 0: X = x param, Y = g_h, identity. MODE 1: X = g_agg, Y = out, ssp.
template <int MODE>
__global__ void __launch_bounds__(256) gemm_kernel(const float* __restrict__ Xparam,
                                                   const float* __restrict__ bias,
                                                   float* __restrict__ Yparam,
                                                   int n_rows) {
    __shared__ __align__(16) float sW[32 * D];   // 16 KB [k][c] tile
    __shared__ __align__(16) float sX[64 * 32];  // 8 KB  [row][k] tile

    const float* __restrict__ X  = (MODE == 0) ? Xparam : g_agg;
    float* __restrict__ Y        = (MODE == 0) ? g_h    : Yparam;
    const float* __restrict__ Wt = g_WT[MODE];

    int r0 = blockIdx.x * 64;
    if (r0 >= n_rows) return;
    int lane = threadIdx.x & 31;
    int warp = threadIdx.x >> 5;

    ull acc[8][2];
    #pragma unroll
    for (int r = 0; r < 8; r++) { acc[r][0] = 0ull; acc[r][1] = 0ull; }

    #pragma unroll
    for (int tile = 0; tile < 4; tile++) {
        __syncthreads();
        for (int t = threadIdx.x; t < 32 * D; t += 256)
            sW[t] = Wt[tile * 32 * D + t];
        for (int t = threadIdx.x; t < 512; t += 256) {   // 512 float4 = 64 rows x 32 k
            int row = t >> 3, c4 = t & 7;
            int r = r0 + row;
            float4 v = make_float4(0.f, 0.f, 0.f, 0.f);
            if (r < n_rows)
                v = *reinterpret_cast<const float4*>(X + (size_t)r * D + tile * 32 + c4 * 4);
            reinterpret_cast<float4*>(sX)[t] = v;
        }
        __syncthreads();

        #pragma unroll
        for (int k = 0; k < 32; k++) {
            ulonglong2 w = *reinterpret_cast<const ulonglong2*>(sW + k * D + 4 * lane);
            #pragma unroll
            for (int r = 0; r < 8; r++) {
                float xv = sX[(warp * 8 + r) * 32 + k];   // broadcast
                ull x2 = pack2(xv, xv);
                acc[r][0] = ffma2(w.x, x2, acc[r][0]);
                acc[r][1] = ffma2(w.y, x2, acc[r][1]);
            }
        }
    }

    float4 b4 = *reinterpret_cast<const float4*>(bias + 4 * lane);
    #pragma unroll
    for (int r = 0; r < 8; r++) {
        int row = r0 + warp * 8 + r;
        if (row < n_rows) {
            float2 p0 = unpack2(acc[r][0]);
            float2 p1 = unpack2(acc[r][1]);
            float4 o;
            o.x = p0.x + b4.x; o.y = p0.y + b4.y;
            o.z = p1.x + b4.z; o.w = p1.y + b4.w;
            if (MODE == 1) { o.x = ssp(o.x); o.y = ssp(o.y); o.z = ssp(o.z); o.w = ssp(o.w); }
            *reinterpret_cast<float4*>(Y + (size_t)row * D + 4 * lane) = o;
        }
    }
}

// ===== Fused pair kernel v4 =====
//  - W_f in registers as packed f32x2 (lane owns 4 channels x 20 rbf)
//  - f_ij staged duplicated (f,f) in smem; inner loop LDS.128 = 2 k's per load
//    (10 broadcast wavefronts/pair, zero pack MOVs)
//  - h[idx_j] gather latency hidden by a DEPTH-4 register prefetch ring
//  - scatter via red.global.add.v4.f32
__global__ void __launch_bounds__(256, 2) pair_kernel(const float* __restrict__ f_ij,
                                                      const int* __restrict__ idx_i,
                                                      const int* __restrict__ idx_j,
                                                      const float* __restrict__ rcut,
                                                      const float* __restrict__ W_f,
                                                      const float* __restrict__ b_f,
                                                      int n_pairs) {
    __shared__ __align__(16) ull sFd[CHUNK * NRBF];  // 20 KB duplicated filter inputs
    __shared__ int   sI[CHUNK];
    __shared__ int   sJ[CHUNK];
    __shared__ float sR[CHUNK];

    int lane = threadIdx.x & 31;
    int warp = threadIdx.x >> 5;

    // ---- Load this lane's 4 weight rows into packed registers (one-time) ----
    ull wp0[NRBF], wp1[NRBF];
    {
        const float4* r0p = reinterpret_cast<const float4*>(W_f + (4 * lane + 0) * NRBF);
        const float4* r1p = reinterpret_cast<const float4*>(W_f + (4 * lane + 1) * NRBF);
        const float4* r2p = reinterpret_cast<const float4*>(W_f + (4 * lane + 2) * NRBF);
        const float4* r3p = reinterpret_cast<const float4*>(W_f + (4 * lane + 3) * NRBF);
        #pragma unroll
        for (int v = 0; v < 5; v++) {
            float4 a = r0p[v], b = r1p[v], c = r2p[v], d = r3p[v];
            wp0[4*v+0] = pack2(a.x, b.x); wp0[4*v+1] = pack2(a.y, b.y);
            wp0[4*v+2] = pack2(a.z, b.z); wp0[4*v+3] = pack2(a.w, b.w);
            wp1[4*v+0] = pack2(c.x, d.x); wp1[4*v+1] = pack2(c.y, d.y);
            wp1[4*v+2] = pack2(c.z, d.z); wp1[4*v+3] = pack2(c.w, d.w);
        }
    }
    float4 bf4 = *reinterpret_cast<const float4*>(b_f + 4 * lane);
    const ull bias0 = pack2(bf4.x, bf4.y);
    const ull bias1 = pack2(bf4.z, bf4.w);

    for (int base = blockIdx.x * CHUNK; base < n_pairs; base += gridDim.x * CHUNK) {
        int cnt = min(CHUNK, n_pairs - base);
        __syncthreads();
        // Stage f duplicated: coalesced LDG.32 + STS.64 per element
        for (int t = threadIdx.x; t < cnt * NRBF; t += 256) {
            float v = f_ij[(size_t)base * NRBF + t];
            sFd[t] = pack2(v, v);
        }
        for (int t = threadIdx.x; t < cnt; t += 256) {
            sI[t] = idx_i[base + t];
            sJ[t] = idx_j[base + t];
            sR[t] = rcut[base + t];
        }
        __syncthreads();

        int q0 = warp * 16;
        int qn = min(16, cnt - q0);
        if (qn <= 0) continue;

        if (qn == 16) {
            // ---- fast path: 16 pairs, depth-4 prefetch ring ----
            float4 hq[4];
            #pragma unroll
            for (int t = 0; t < 4; t++)
                hq[t] = *reinterpret_cast<const float4*>(
                    g_h + (size_t)sJ[q0 + t] * D + 4 * lane);

            #pragma unroll 4
            for (int q = 0; q < 16; q++) {
                float4 h4 = hq[q & 3];
                if (q + 4 < 16)
                    hq[q & 3] = *reinterpret_cast<const float4*>(
                        g_h + (size_t)sJ[q0 + q + 4] * D + 4 * lane);

                const ull* f = sFd + (q0 + q) * NRBF;
                int i = sI[q0 + q];
                float rc = sR[q0 + q];

                ull a0 = bias0, a1 = bias1;
                #pragma unroll
                for (int k2 = 0; k2 < NRBF / 2; k2++) {
                    ulonglong2 ff = *reinterpret_cast<const ulonglong2*>(f + 2 * k2);
                    a0 = ffma2(wp0[2 * k2], ff.x, a0);
                    a1 = ffma2(wp1[2 * k2], ff.x, a1);
                    a0 = ffma2(wp0[2 * k2 + 1], ff.y, a0);
                    a1 = ffma2(wp1[2 * k2 + 1], ff.y, a1);
                }
                float2 p0 = unpack2(a0);
                float2 p1 = unpack2(a1);
                float s0 = ssp(p0.x) * rc;
                float s1 = ssp(p0.y) * rc;
                float s2 = ssp(p1.x) * rc;
                float s3 = ssp(p1.y) * rc;

                float vx = h4.x * s0, vy = h4.y * s1, vz = h4.z * s2, vw = h4.w * s3;
                float* dst = g_agg + (size_t)i * D + 4 * lane;
                asm volatile("red.global.add.v4.f32 [%0], {%1,%2,%3,%4};"
                             :: "l"(dst), "f"(vx), "f"(vy), "f"(vz), "f"(vw)
                             : "memory");
            }
        } else {
            // ---- tail path: simple ----
            for (int q = q0; q < q0 + qn; q++) {
                const ull* f = sFd + q * NRBF;
                int i = sI[q], j = sJ[q];
                float rc = sR[q];
                const float4 h4 = *reinterpret_cast<const float4*>(
                    g_h + (size_t)j * D + 4 * lane);

                ull a0 = bias0, a1 = bias1;
                #pragma unroll
                for (int k2 = 0; k2 < NRBF / 2; k2++) {
                    ulonglong2 ff = *reinterpret_cast<const ulonglong2*>(f + 2 * k2);
                    a0 = ffma2(wp0[2 * k2], ff.x, a0);
                    a1 = ffma2(wp1[2 * k2], ff.x, a1);
                    a0 = ffma2(wp0[2 * k2 + 1], ff.y, a0);
                    a1 = ffma2(wp1[2 * k2 + 1], ff.y, a1);
                }
                float2 p0 = unpack2(a0);
                float2 p1 = unpack2(a1);
                float s0 = ssp(p0.x) * rc;
                float s1 = ssp(p0.y) * rc;
                float s2 = ssp(p1.x) * rc;
                float s3 = ssp(p1.y) * rc;

                float vx = h4.x * s0, vy = h4.y * s1, vz = h4.z * s2, vw = h4.w * s3;
                float* dst = g_agg + (size_t)i * D + 4 * lane;
                asm volatile("red.global.add.v4.f32 [%0], {%1,%2,%3,%4};"
                             :: "l"(dst), "f"(vx), "f"(vy), "f"(vz), "f"(vw)
                             : "memory");
            }
        }
    }
}

extern "C" void kernel_launch(void* const* d_in, const int* in_sizes, int n_in,
                              void* d_out, int out_size) {
    const float* x     = (const float*)d_in[0];
    const float* f_ij  = (const float*)d_in[1];
    const int*   idx_i = (const int*)  d_in[2];
    const int*   idx_j = (const int*)  d_in[3];
    const float* rcut  = (const float*)d_in[4];
    const float* W_in  = (const float*)d_in[5];
    const float* b_in  = (const float*)d_in[6];
    const float* W_f   = (const float*)d_in[7];
    const float* b_f   = (const float*)d_in[8];
    const float* W_out = (const float*)d_in[9];
    const float* b_out = (const float*)d_in[10];
    float* out = (float*)d_out;
    (void)n_in; (void)out_size;

    int n_atoms = in_sizes[0] / D;
    int n_pairs = in_sizes[2];

    prep_kernel<<<(D * D + 255) / 256, 256>>>(W_in, W_out);
    int n4 = (n_atoms * D) / 4;
    zero_kernel<<<(n4 + 255) / 256, 256>>>(n4);

    int gblocks = (n_atoms + 63) / 64;
    gemm_kernel<0><<<gblocks, 256>>>(x, b_in, nullptr, n_atoms);

    pair_kernel<<<1184, 256>>>(f_ij, idx_i, idx_j, rcut, W_f, b_f, n_pairs);

    gemm_kernel<1><<<gblocks, 256>>>(nullptr, b_out, out, n_atoms);
}

// round 8
// speedup vs baseline: 1.0565x; 1.0565x over previous
#include <cuda_runtime.h>
#include <math.h>

#define D        128
#define NRBF     20
#define MAX_ATOMS 40960
#define CHUNK    128   // pairs staged per block iteration (32 per warp, 2 warps/pair)

// Scratch (alloc-free: __device__ globals)
__device__ __align__(16) float g_h[MAX_ATOMS * D];      // 20.5 MB
__device__ __align__(16) float g_agg[MAX_ATOMS * D];    // 20.5 MB
__device__ __align__(16) float g_WT[2][D * D];          // transposed W_in / W_out

typedef unsigned long long ull;

__device__ __forceinline__ ull pack2(float a, float b) {
    ull r; asm("mov.b64 %0, {%1,%2};" : "=l"(r) : "f"(a), "f"(b)); return r;
}
__device__ __forceinline__ float2 unpack2(ull v) {
    float2 f; asm("mov.b64 {%0,%1}, %2;" : "=f"(f.x), "=f"(f.y) : "l"(v)); return f;
}
__device__ __forceinline__ ull ffma2(ull a, ull b, ull c) {
    ull d; asm("fma.rn.f32x2 %0, %1, %2, %3;" : "=l"(d) : "l"(a), "l"(b), "l"(c)); return d;
}

__device__ __forceinline__ float ssp(float x) {
    // softplus(x) - ln2, fast+stable: max(x,0) + log(1+exp(-|x|)) - ln2
    float e = __expf(-fabsf(x));
    return fmaxf(x, 0.0f) + __logf(1.0f + e) - 0.69314718056f;
}

// Transpose W_in / W_out ([c][k] -> [k][c]) for coalesced conflict-free GEMM tiles.
__global__ void prep_kernel(const float* __restrict__ Win, const float* __restrict__ Wout) {
    int t = blockIdx.x * blockDim.x + threadIdx.x;
    if (t < D * D) {
        int c = t >> 7, k = t & 127;
        g_WT[0][k * D + c] = Win[t];
        g_WT[1][k * D + c] = Wout[t];
    }
}

__global__ void zero_kernel(int n4) {
    int t = blockIdx.x * blockDim.x + threadIdx.x;
    if (t < n4) reinterpret_cast<float4*>(g_agg)[t] = make_float4(0.f, 0.f, 0.f, 0.f);
}

// ===== GEMM: exact R5 version (known good) =====
template <int MODE>
__global__ void __launch_bounds__(256) gemm_kernel(const float* __restrict__ Xparam,
                                                   const float* __restrict__ bias,
                                                   float* __restrict__ Yparam,
                                                   int n_rows) {
    __shared__ __align__(16) float sW[32 * D];   // 16 KB [k][c] tile
    __shared__ __align__(16) float sX[64 * 32];  // 8 KB  [row][k] tile

    const float* __restrict__ X  = (MODE == 0) ? Xparam : g_agg;
    float* __restrict__ Y        = (MODE == 0) ? g_h    : Yparam;
    const float* __restrict__ Wt = g_WT[MODE];

    int r0 = blockIdx.x * 64;
    if (r0 >= n_rows) return;
    int lane = threadIdx.x & 31;
    int warp = threadIdx.x >> 5;

    ull acc[8][2];
    #pragma unroll
    for (int r = 0; r < 8; r++) { acc[r][0] = 0ull; acc[r][1] = 0ull; }

    #pragma unroll
    for (int tile = 0; tile < 4; tile++) {
        __syncthreads();
        for (int t = threadIdx.x; t < 32 * D; t += 256)
            sW[t] = Wt[tile * 32 * D + t];
        for (int t = threadIdx.x; t < 512; t += 256) {   // 512 float4 = 64 rows x 32 k
            int row = t >> 3, c4 = t & 7;
            int r = r0 + row;
            float4 v = make_float4(0.f, 0.f, 0.f, 0.f);
            if (r < n_rows)
                v = *reinterpret_cast<const float4*>(X + (size_t)r * D + tile * 32 + c4 * 4);
            reinterpret_cast<float4*>(sX)[t] = v;
        }
        __syncthreads();

        #pragma unroll
        for (int k = 0; k < 32; k++) {
            ulonglong2 w = *reinterpret_cast<const ulonglong2*>(sW + k * D + 4 * lane);
            #pragma unroll
            for (int r = 0; r < 8; r++) {
                float xv = sX[(warp * 8 + r) * 32 + k];   // broadcast
                ull x2 = pack2(xv, xv);
                acc[r][0] = ffma2(w.x, x2, acc[r][0]);
                acc[r][1] = ffma2(w.y, x2, acc[r][1]);
            }
        }
    }

    float4 b4 = *reinterpret_cast<const float4*>(bias + 4 * lane);
    #pragma unroll
    for (int r = 0; r < 8; r++) {
        int row = r0 + warp * 8 + r;
        if (row < n_rows) {
            float2 p0 = unpack2(acc[r][0]);
            float2 p1 = unpack2(acc[r][1]);
            float4 o;
            o.x = p0.x + b4.x; o.y = p0.y + b4.y;
            o.z = p1.x + b4.z; o.w = p1.y + b4.w;
            if (MODE == 1) { o.x = ssp(o.x); o.y = ssp(o.y); o.z = ssp(o.z); o.w = ssp(o.w); }
            *reinterpret_cast<float4*>(Y + (size_t)row * D + 4 * lane) = o;
        }
    }
}

// ===== Fused pair kernel v5: occupancy-first =====
//  - 2 warps per pair: warps 0-3 own channels [0,64), warps 4-7 own [64,128)
//  - lane owns 2 channels -> W_f registers = 20 packed ull (40 regs, not 80)
//  - launch_bounds(256,3): 24 warps/SM (was 16)
//  - f_ij staged duplicated (f,f) via VECTORIZED float4->ulonglong2 staging;
//    inner loop: 10x LDS.128 broadcast, zero pack MOVs
//  - gather LDG.64, scatter red.global.add.v2.f32
__global__ void __launch_bounds__(256, 3) pair_kernel(const float* __restrict__ f_ij,
                                                      const int* __restrict__ idx_i,
                                                      const int* __restrict__ idx_j,
                                                      const float* __restrict__ rcut,
                                                      const float* __restrict__ W_f,
                                                      const float* __restrict__ b_f,
                                                      int n_pairs) {
    __shared__ __align__(16) ull sFd[CHUNK * NRBF];  // 20 KB duplicated filter inputs
    __shared__ int   sI[CHUNK];
    __shared__ int   sJ[CHUNK];
    __shared__ float sR[CHUNK];

    int lane = threadIdx.x & 31;
    int warp = threadIdx.x >> 5;
    int half = warp >> 2;          // channel half: 0 or 1
    int sub  = warp & 3;           // pair subrange within chunk
    int c0   = half * 64 + 2 * lane;   // first of this lane's 2 channels

    // ---- This lane's 2 weight rows, packed (one-time): 20 ull = 40 regs ----
    ull wp[NRBF];
    {
        const float4* r0p = reinterpret_cast<const float4*>(W_f + (size_t)c0 * NRBF);
        const float4* r1p = reinterpret_cast<const float4*>(W_f + (size_t)(c0 + 1) * NRBF);
        #pragma unroll
        for (int v = 0; v < 5; v++) {
            float4 a = r0p[v], b = r1p[v];
            wp[4*v+0] = pack2(a.x, b.x);
            wp[4*v+1] = pack2(a.y, b.y);
            wp[4*v+2] = pack2(a.z, b.z);
            wp[4*v+3] = pack2(a.w, b.w);
        }
    }
    const ull bias2 = pack2(b_f[c0], b_f[c0 + 1]);

    for (int base = blockIdx.x * CHUNK; base < n_pairs; base += gridDim.x * CHUNK) {
        int cnt = min(CHUNK, n_pairs - base);
        __syncthreads();
        // Vectorized duplicated staging: float4 load -> 2x ulonglong2 store
        if (cnt == CHUNK) {
            const float4* src = reinterpret_cast<const float4*>(f_ij + (size_t)base * NRBF);
            for (int t = threadIdx.x; t < CHUNK * NRBF / 4; t += 256) {
                float4 v = src[t];
                ulonglong2* dst = reinterpret_cast<ulonglong2*>(&sFd[t * 4]);
                dst[0] = make_ulonglong2(pack2(v.x, v.x), pack2(v.y, v.y));
                dst[1] = make_ulonglong2(pack2(v.z, v.z), pack2(v.w, v.w));
            }
        } else {
            for (int t = threadIdx.x; t < cnt * NRBF; t += 256) {
                float v = f_ij[(size_t)base * NRBF + t];
                sFd[t] = pack2(v, v);
            }
        }
        for (int t = threadIdx.x; t < cnt; t += 256) {
            sI[t] = idx_i[base + t];
            sJ[t] = idx_j[base + t];
            sR[t] = rcut[base + t];
        }
        __syncthreads();

        int q0 = sub * 32;
        int qend = min(q0 + 32, cnt);
        for (int q = q0; q < qend; q++) {
            const ull* f = sFd + q * NRBF;
            int i = sI[q], j = sJ[q];
            float rc = sR[q];

            // prefetch neighbor features (2 floats for this lane's channels)
            const float2 h2 = *reinterpret_cast<const float2*>(
                g_h + (size_t)j * D + c0);

            ull acc = bias2;
            #pragma unroll
            for (int k2 = 0; k2 < NRBF / 2; k2++) {
                ulonglong2 ff = *reinterpret_cast<const ulonglong2*>(f + 2 * k2);
                acc = ffma2(wp[2 * k2],     ff.x, acc);
                acc = ffma2(wp[2 * k2 + 1], ff.y, acc);
            }
            float2 p = unpack2(acc);
            float s0 = ssp(p.x) * rc;
            float s1 = ssp(p.y) * rc;

            float vx = h2.x * s0, vy = h2.y * s1;
            float* dst = g_agg + (size_t)i * D + c0;
            asm volatile("red.global.add.v2.f32 [%0], {%1,%2};"
                         :: "l"(dst), "f"(vx), "f"(vy)
                         : "memory");
        }
    }
}

extern "C" void kernel_launch(void* const* d_in, const int* in_sizes, int n_in,
                              void* d_out, int out_size) {
    const float* x     = (const float*)d_in[0];
    const float* f_ij  = (const float*)d_in[1];
    const int*   idx_i = (const int*)  d_in[2];
    const int*   idx_j = (const int*)  d_in[3];
    const float* rcut  = (const float*)d_in[4];
    const float* W_in  = (const float*)d_in[5];
    const float* b_in  = (const float*)d_in[6];
    const float* W_f   = (const float*)d_in[7];
    const float* b_f   = (const float*)d_in[8];
    const float* W_out = (const float*)d_in[9];
    const float* b_out = (const float*)d_in[10];
    float* out = (float*)d_out;
    (void)n_in; (void)out_size;

    int n_atoms = in_sizes[0] / D;
    int n_pairs = in_sizes[2];

    prep_kernel<<<(D * D + 255) / 256, 256>>>(W_in, W_out);
    int n4 = (n_atoms * D) / 4;
    zero_kernel<<<(n4 + 255) / 256, 256>>>(n4);

    int gblocks = (n_atoms + 63) / 64;
    gemm_kernel<0><<<gblocks, 256>>>(x, b_in, nullptr, n_atoms);

    pair_kernel<<<1184, 256>>>(f_ij, idx_i, idx_j, rcut, W_f, b_f, n_pairs);

    gemm_kernel<1><<<gblocks, 256>>>(nullptr, b_out, out, n_atoms);
}